// round 7
// baseline (speedup 1.0000x reference)
#include <cuda_runtime.h>
#include <stdint.h>

// Problem geometry (fixed: act = (4, 4096, 4096) fp32)
#define DCOL 4096
#define GRP  32
#define NG   (DCOL/GRP)      // 128 groups (reduced over batch+rows+group)
#define F4_PER_ROW (DCOL/4)  // 1024 float4 per row

// Scratch (__device__ globals; no allocation allowed)
__device__ unsigned int g_maxbits[NG];

// ---------------------------------------------------------------------------
__global__ void k_zero()
{
    if (threadIdx.x < NG) g_maxbits[threadIdx.x] = 0u;
}

__device__ __forceinline__ float max4abs(float4 v)
{
    return fmaxf(fmaxf(fabsf(v.x), fabsf(v.y)), fmaxf(fabsf(v.z), fabsf(v.w)));
}

__device__ __forceinline__ float4 quant4(float4 v, float inv_s8, float s8)
{
    float4 o;
    o.x = copysignf(rintf(fminf(fabsf(v.x) * inv_s8, 8.0f)) * s8, v.x);
    o.y = copysignf(rintf(fminf(fabsf(v.y) * inv_s8, 8.0f)) * s8, v.y);
    o.z = copysignf(rintf(fminf(fabsf(v.z) * inv_s8, 8.0f)) * s8, v.z);
    o.w = copysignf(rintf(fminf(fabsf(v.w) * inv_s8, 8.0f)) * s8, v.w);
    return o;
}

// ---------------------------------------------------------------------------
// Pass 1: per-group max|x|. Thread j owns float4-column j (group j>>3).
// Grid-stride over rows, 8 loads front-batched per iteration (high MLP),
// streaming loads (no L2 allocation — reuse lever proven dead in R4/R6).
// ---------------------------------------------------------------------------
__global__ __launch_bounds__(1024, 2)
void k_pass1(const float4* __restrict__ act, int rows)
{
    const int j = threadIdx.x;
    const int stride = gridDim.x;
    float m = 0.0f;

    int r = blockIdx.x;
    for (; r + 7 * stride < rows; r += 8 * stride) {
        float4 v0 = __ldcs(&act[(size_t)(r + 0 * stride) * F4_PER_ROW + j]);
        float4 v1 = __ldcs(&act[(size_t)(r + 1 * stride) * F4_PER_ROW + j]);
        float4 v2 = __ldcs(&act[(size_t)(r + 2 * stride) * F4_PER_ROW + j]);
        float4 v3 = __ldcs(&act[(size_t)(r + 3 * stride) * F4_PER_ROW + j]);
        float4 v4 = __ldcs(&act[(size_t)(r + 4 * stride) * F4_PER_ROW + j]);
        float4 v5 = __ldcs(&act[(size_t)(r + 5 * stride) * F4_PER_ROW + j]);
        float4 v6 = __ldcs(&act[(size_t)(r + 6 * stride) * F4_PER_ROW + j]);
        float4 v7 = __ldcs(&act[(size_t)(r + 7 * stride) * F4_PER_ROW + j]);
        float a = fmaxf(fmaxf(max4abs(v0), max4abs(v1)), fmaxf(max4abs(v2), max4abs(v3)));
        float b = fmaxf(fmaxf(max4abs(v4), max4abs(v5)), fmaxf(max4abs(v6), max4abs(v7)));
        m = fmaxf(m, fmaxf(a, b));
    }
    for (; r < rows; r += stride)
        m = fmaxf(m, max4abs(__ldcs(&act[(size_t)r * F4_PER_ROW + j])));

    // 8-lane reduce within the group (j>>3 constant under xor 4,2,1)
    m = fmaxf(m, __shfl_xor_sync(0xffffffffu, m, 4));
    m = fmaxf(m, __shfl_xor_sync(0xffffffffu, m, 2));
    m = fmaxf(m, __shfl_xor_sync(0xffffffffu, m, 1));
    if ((j & 7) == 0)
        atomicMax(&g_maxbits[j >> 3], __float_as_uint(m));
}

// ---------------------------------------------------------------------------
// Pass 2: quantize. Scales derived in-kernel from g_maxbits (no k_finalize
// launch). 4 rows per iteration, loads front-batched before any stores.
// Block 0 also writes the 128 exps to the output tail.
// ---------------------------------------------------------------------------
__global__ __launch_bounds__(1024, 2)
void k_pass2(const float4* __restrict__ act, float4* __restrict__ q,
             float* __restrict__ exps_out, int rows)
{
    const int j = threadIdx.x;
    const int g = j >> 3;

    // Derive this thread's scale (atomics live in L2 -> ldcg)
    const float ma = __uint_as_float(__ldcg(&g_maxbits[g]));
    float s;
    if (ma > 0.0f) {
        int e = (int)((__float_as_uint(ma) >> 23) & 0xFFu) - 127;  // exact floor(log2)
        s = __uint_as_float((unsigned)(e + 127) << 23);            // 2^e exact
    } else {
        s = 1.0f;
    }
    const float inv_s8 = 8.0f / s;     // exact power of 2
    const float s8     = s * 0.125f;   // exact power of 2

    if (blockIdx.x == 0 && j < NG) {
        const float m2 = __uint_as_float(__ldcg(&g_maxbits[j]));
        exps_out[j] = (m2 > 0.0f)
                    ? (float)((int)((__float_as_uint(m2) >> 23) & 0xFFu) - 127)
                    : 0.0f;
    }

    const int stride = gridDim.x;
    int r = blockIdx.x;
    for (; r + 3 * stride < rows; r += 4 * stride) {
        const size_t i0 = (size_t)(r + 0 * stride) * F4_PER_ROW + j;
        const size_t i1 = (size_t)(r + 1 * stride) * F4_PER_ROW + j;
        const size_t i2 = (size_t)(r + 2 * stride) * F4_PER_ROW + j;
        const size_t i3 = (size_t)(r + 3 * stride) * F4_PER_ROW + j;
        float4 v0 = __ldcs(&act[i0]);
        float4 v1 = __ldcs(&act[i1]);
        float4 v2 = __ldcs(&act[i2]);
        float4 v3 = __ldcs(&act[i3]);
        __stcs(&q[i0], quant4(v0, inv_s8, s8));
        __stcs(&q[i1], quant4(v1, inv_s8, s8));
        __stcs(&q[i2], quant4(v2, inv_s8, s8));
        __stcs(&q[i3], quant4(v3, inv_s8, s8));
    }
    for (; r < rows; r += stride) {
        const size_t i0 = (size_t)r * F4_PER_ROW + j;
        __stcs(&q[i0], quant4(__ldcs(&act[i0]), inv_s8, s8));
    }
}

// ---------------------------------------------------------------------------
extern "C" void kernel_launch(void* const* d_in, const int* in_sizes, int n_in,
                              void* d_out, int out_size)
{
    const float4* act = (const float4*)d_in[0];
    float*        out = (float*)d_out;
    const int total = in_sizes[0];   // 67108864
    const int rows  = total / DCOL;  // 16384

    k_zero<<<1, 128>>>();
    k_pass1<<<512, 1024>>>(act, rows);
    k_pass2<<<1024, 1024>>>(act, (float4*)d_out, out + (size_t)total, rows);
}